// round 9
// baseline (speedup 1.0000x reference)
#include <cuda_runtime.h>
#include <cstdint>

// 1024 blocks x 128 threads. Block bk: ipair = bk>>3 (row-pair of the 256x32
// idx matrix), jg = bk&7 (column group of 4) -> 2x4 tile (8 rows).
// Warp w (0..3) handles slots (dm=0,dn=w) and (dm=1,dn=w):
//   row[tt] = (2*ipair+tt)*32 + 4*jg + w.
// All 4 idx entries of each packed word live inside one block -> local pack.
//
// Table trick: s_a[A][0..7] = |grid[A<<8]| (only component 7 can be negative),
// s_a[A][8] = na_signed (norm with a7's sign folded into the sign bit).
// Then sign(t_j) = sign(x_j): parity & sign masks precompute per ROW.

__global__ void __launch_bounds__(128, 8) e8p_fused_kernel(
    const float* __restrict__ X,
    const float* __restrict__ grid,
    const float* __restrict__ grid_norm,
    float* __restrict__ out)
{
    __shared__ __align__(16) float s_a[256][12];   // stride 12 -> LDS.128 conflict-free
    __shared__ int s_bestc[8];

    const int tid = threadIdx.x;
    #pragma unroll
    for (int it = 0; it < 2; it++) {
        const int A = tid + it * 128;
        const float4* g4 = reinterpret_cast<const float4*>(grid + ((size_t)A << 11));
        float4 a0 = g4[0], a1 = g4[1];
        const float na = grid_norm[A << 8];
        float4* d4 = reinterpret_cast<float4*>(s_a[A]);
        d4[0] = make_float4(fabsf(a0.x), fabsf(a0.y), fabsf(a0.z), fabsf(a0.w));
        d4[1] = make_float4(fabsf(a1.x), fabsf(a1.y), fabsf(a1.z), fabsf(a1.w));
        s_a[A][8] = (a1.w < 0.f) ? -na : na;       // fold sign(a7) into na
    }
    __syncthreads();

    const int warp = tid >> 5, lane = tid & 31;
    const int ipair = blockIdx.x >> 3;             // 0..127
    const int jg    = blockIdx.x & 7;              // 0..7

    // Component j of the value vector <- bit SHUF[j] of the sign field.
    // SHUF = {0,4,1,5,2,6,3,7} -> BITS[j] = 1 << SHUF[j].
    constexpr unsigned BITS[8] = {1u<<0, 1u<<4, 1u<<1, 1u<<5, 1u<<2, 1u<<6, 1u<<3, 1u<<7};

    int   row[2];
    float x[2][8], p1c[2];
    unsigned maskx[2][2];                          // [tt][parity] sign masks (BITS domain)
    int px[2][2];                                  // parity bit in sign position
    #pragma unroll
    for (int tt = 0; tt < 2; tt++) {
        row[tt] = (2 * ipair + tt) * 32 + 4 * jg + warp;
        const float4* xr4 = reinterpret_cast<const float4*>(X + (size_t)row[tt] * 8);
        float4 v0 = xr4[0], v1 = xr4[1];
        x[tt][0]=v0.x; x[tt][1]=v0.y; x[tt][2]=v0.z; x[tt][3]=v0.w;
        x[tt][4]=v1.x; x[tt][5]=v1.y; x[tt][6]=v1.z; x[tt][7]=v1.w;
        float sx = 0.f;
        unsigned m0 = 0, m1 = 0;
        #pragma unroll
        for (int j = 0; j < 8; j++) {
            sx += x[tt][j];
            if (x[tt][j] < 0.f)          m0 |= BITS[j];
            if (x[tt][j] + 0.25f < 0.f)  m1 |= BITS[j];
        }
        p1c[tt] = -0.5f * sx - 0.5f;
        maskx[tt][0] = m0;  px[tt][0] = (__popc(m0) & 1) << 31;
        maskx[tt][1] = m1;  px[tt][1] = (__popc(m1) & 1) << 31;
    }

    float best[2] = {-1e30f, -1e30f};
    int   bA[2]   = {0, 0};

    #pragma unroll
    for (int k = 0; k < 8; k++) {
        const int A = lane + (k << 5);
        float a[8];
        {
            const float4* p4 = reinterpret_cast<const float4*>(s_a[A]);
            float4 a0 = p4[0], a1 = p4[1];
            a[0]=a0.x; a[1]=a0.y; a[2]=a0.z; a[3]=a0.w;
            a[4]=a1.x; a[5]=a1.y; a[6]=a1.z; a[7]=a1.w;
        }
        const float nas  = s_a[A][8];
        const int   ns   = __float_as_int(nas);    // sign bit = sign(a7)
        const float nabs = fabsf(nas);

        #pragma unroll
        for (int tt = 0; tt < 2; tt++) {
            float t0[8], t1[8];
            #pragma unroll
            for (int j = 0; j < 8; j++) {
                t0[j] = x[tt][j] * a[j];                   // sign == sign(x_j)
                t1[j] = fmaf(0.25f, a[j], t0[j]);          // == (x+0.25)*|a| (1 rnd)
            }
            // p = 0
            float S0 = ((fabsf(t0[0]) + fabsf(t0[1])) + (fabsf(t0[2]) + fabsf(t0[3])))
                     + ((fabsf(t0[4]) + fabsf(t0[5])) + (fabsf(t0[6]) + fabsf(t0[7])));
            float mn0 = fminf(fminf(fminf(fabsf(t0[0]), fabsf(t0[1])),
                                    fminf(fabsf(t0[2]), fabsf(t0[3]))),
                              fminf(fminf(fabsf(t0[4]), fabsf(t0[5])),
                                    fminf(fabsf(t0[6]), fabsf(t0[7]))));
            float Sp0 = ((ns ^ px[tt][0]) < 0) ? fmaf(-2.f, mn0, S0) : S0;
            float sc0 = fmaf(2.f, Sp0, -nabs);
            // p = 1
            float S1 = ((fabsf(t1[0]) + fabsf(t1[1])) + (fabsf(t1[2]) + fabsf(t1[3])))
                     + ((fabsf(t1[4]) + fabsf(t1[5])) + (fabsf(t1[6]) + fabsf(t1[7])));
            float mn1 = fminf(fminf(fminf(fabsf(t1[0]), fabsf(t1[1])),
                                    fminf(fabsf(t1[2]), fabsf(t1[3]))),
                              fminf(fminf(fabsf(t1[4]), fabsf(t1[5])),
                                    fminf(fabsf(t1[6]), fabsf(t1[7]))));
            float Sp1 = ((ns ^ px[tt][1]) < 0) ? fmaf(-2.f, mn1, S1) : S1;
            float sc1 = fmaf(2.f, Sp1, -nabs) + p1c[tt];

            float scm = fmaxf(sc0, sc1);                   // parity re-decided at winner
            if (scm > best[tt]) { best[tt] = scm; bA[tt] = A; }   // first-wins: lowest A
        }
    }

    #pragma unroll
    for (int tt = 0; tt < 2; tt++) {
        // Warp argmax (butterfly; tie -> lowest A, matching argmax first-max).
        float b = best[tt]; int cA = bA[tt];
        #pragma unroll
        for (int off = 16; off; off >>= 1) {
            float ob = __shfl_xor_sync(0xffffffffu, b,  off);
            int   oc = __shfl_xor_sync(0xffffffffu, cA, off);
            if (ob > b || (ob == b && oc < cA)) { b = ob; cA = oc; }
        }

        // Winner recompute (all lanes, broadcast LDS): decide parity, sign mask,
        // argmin flip — identical formulas to the scan.
        const float* av = s_a[cA];
        const float nas  = av[8];
        const int   ns   = __float_as_int(nas);
        const float nabs = fabsf(nas);
        float t0[8], t1[8];
        #pragma unroll
        for (int j = 0; j < 8; j++) {
            t0[j] = x[tt][j] * av[j];
            t1[j] = fmaf(0.25f, av[j], t0[j]);
        }
        float S0 = ((fabsf(t0[0]) + fabsf(t0[1])) + (fabsf(t0[2]) + fabsf(t0[3])))
                 + ((fabsf(t0[4]) + fabsf(t0[5])) + (fabsf(t0[6]) + fabsf(t0[7])));
        float mn0 = fminf(fminf(fminf(fabsf(t0[0]), fabsf(t0[1])),
                                fminf(fabsf(t0[2]), fabsf(t0[3]))),
                          fminf(fminf(fabsf(t0[4]), fabsf(t0[5])),
                                fminf(fabsf(t0[6]), fabsf(t0[7]))));
        float Sp0 = ((ns ^ px[tt][0]) < 0) ? fmaf(-2.f, mn0, S0) : S0;
        float sc0 = fmaf(2.f, Sp0, -nabs);
        float S1 = ((fabsf(t1[0]) + fabsf(t1[1])) + (fabsf(t1[2]) + fabsf(t1[3])))
                 + ((fabsf(t1[4]) + fabsf(t1[5])) + (fabsf(t1[6]) + fabsf(t1[7])));
        float mn1 = fminf(fminf(fminf(fabsf(t1[0]), fabsf(t1[1])),
                                fminf(fabsf(t1[2]), fabsf(t1[3]))),
                          fminf(fminf(fabsf(t1[4]), fabsf(t1[5])),
                                fminf(fabsf(t1[6]), fabsf(t1[7]))));
        float Sp1 = ((ns ^ px[tt][1]) < 0) ? fmaf(-2.f, mn1, S1) : S1;
        float sc1 = fmaf(2.f, Sp1, -nabs) + p1c[tt];

        const int pw = (sc1 > sc0) ? 1 : 0;               // p0 wins exact ties
        unsigned m = maskx[tt][pw] ^ ((ns < 0) ? 0x80u : 0u);
        float mnv = 1e30f; unsigned mnbit = 0;
        #pragma unroll
        for (int j = 0; j < 8; j++) {
            float at = fabsf(pw ? t1[j] : t0[j]);
            if (at < mnv) { mnv = at; mnbit = BITS[j]; }  // strict: first min
        }
        if (__popc(m) & 1) m ^= mnbit;
        const int bestc = (cA << 8) | ((int)m ^ pw);      // p=1 flips sign-field bit 0

        if (lane < 8) {
            out[(size_t)row[tt] * 8 + lane] = grid[(size_t)bestc * 8 + lane];  // vals
        }
        if (lane == 0) {
            out[65536 + row[tt]] = (float)bestc;          // idxs
            s_bestc[tt * 4 + warp] = bestc;               // slot = dm*4 + dn
        }
    }
    __syncthreads();

    // ---- Block-local _pack_idxs (int32 / x64-disabled semantics: the reference's
    //      sign32 << 32 saturates to 0 in XLA; packed = int32 wrap of abs32).
    if (tid < 2) {
        const int jj = tid;                               // jj = 0,1
        const int j  = 2 * jg + jj;
        int q00 = s_bestc[      2 * jj    ];              // (dm=0, dn=2jj)   -> (2i,   2j)
        int q10 = s_bestc[4 +   2 * jj    ];              // (dm=1, dn=2jj)   -> (2i+1, 2j)
        int q01 = s_bestc[      2 * jj + 1];              // (dm=0, dn=2jj+1) -> (2i,   2j+1)
        int q11 = s_bestc[4 +   2 * jj + 1];              // (dm=1, dn=2jj+1) -> (2i+1, 2j+1)

        unsigned abs32 = (unsigned)(q00 >> 8)
                       | ((unsigned)(q10 >> 8) << 8)
                       | ((unsigned)(q01 >> 8) << 16)
                       | ((unsigned)(q11 >> 8) << 24);

        // L from (i, j): L = (i>>3)<<7 | (j>>2)<<5 | (i&7)<<2 | (j&3)
        const int i = ipair;
        const int L = ((i >> 3) << 7) | ((j >> 2) << 5) | ((i & 7) << 2) | (j & 3);
        out[73728 + L] = (float)(int)abs32;               // int32 wrap, then f32 cast
    }
}

extern "C" void kernel_launch(void* const* d_in, const int* in_sizes, int n_in,
                              void* d_out, int out_size)
{
    const float* X         = (const float*)d_in[0];   // 256*32*8 = 65536
    const float* grid      = (const float*)d_in[1];   // 65536*8
    const float* grid_norm = (const float*)d_in[2];   // 65536
    float* out = (float*)d_out;                       // [vals | idxs | packed] fp32

    e8p_fused_kernel<<<1024, 128>>>(X, grid, grid_norm, out);
}

// round 10
// speedup vs baseline: 1.0151x; 1.0151x over previous
#include <cuda_runtime.h>
#include <cstdint>

// 512 blocks x 256 threads. Block bk: ipair = bk>>2 (row-pair of the 256x32
// idx matrix), jg0 = 2*(bk&3); block covers tiles jg0, jg0+1 (16 rows).
// Warp w: dm=w>>2, dn=w&3; handles rows row[tt] = (2*ipair+dm)*32 + 4*(jg0+tt)+dn.
// All 4 idx entries of each packed word live inside one block -> local pack.
//
// Table trick: s_a[A][0..7] = |grid[A<<8]| (only component 7 can be negative),
// s_a[A][8] = norm with sign(a7) folded into its sign bit.
// Then sign(t_j) = sign(x_j): parity & sign masks precompute per ROW.

__global__ void __launch_bounds__(256, 4) e8p_fused_kernel(
    const float* __restrict__ X,
    const float* __restrict__ grid,
    const float* __restrict__ grid_norm,
    float* __restrict__ out)
{
    __shared__ __align__(16) float s_a[256][12];   // stride 12 -> LDS.128 conflict-free
    __shared__ int s_bestc[16];

    const int tid = threadIdx.x;
    {
        const int A = tid;                         // exactly 256 threads: one round
        const float4* g4 = reinterpret_cast<const float4*>(grid + ((size_t)A << 11));
        float4 a0 = g4[0], a1 = g4[1];
        const float na = grid_norm[A << 8];
        float4* d4 = reinterpret_cast<float4*>(s_a[A]);
        d4[0] = make_float4(fabsf(a0.x), fabsf(a0.y), fabsf(a0.z), fabsf(a0.w));
        d4[1] = make_float4(fabsf(a1.x), fabsf(a1.y), fabsf(a1.z), fabsf(a1.w));
        s_a[A][8] = (a1.w < 0.f) ? -na : na;       // fold sign(a7) into na
    }
    __syncthreads();

    const int warp = tid >> 5, lane = tid & 31;
    const int ipair = blockIdx.x >> 2;             // 0..127
    const int jg0   = (blockIdx.x & 3) * 2;        // 0,2,4,6
    const int dm = warp >> 2, dn = warp & 3;

    // Component j of the value vector <- bit SHUF[j] of the sign field.
    // SHUF = {0,4,1,5,2,6,3,7} -> BITS[j] = 1 << SHUF[j].
    constexpr unsigned BITS[8] = {1u<<0, 1u<<4, 1u<<1, 1u<<5, 1u<<2, 1u<<6, 1u<<3, 1u<<7};

    int   row[2];
    float x[2][8], p1c[2];
    unsigned maskx[2][2];                          // [tt][parity] sign masks (BITS domain)
    int px[2][2];                                  // parity bit in sign position
    #pragma unroll
    for (int tt = 0; tt < 2; tt++) {
        row[tt] = (2 * ipair + dm) * 32 + 4 * (jg0 + tt) + dn;
        const float4* xr4 = reinterpret_cast<const float4*>(X + (size_t)row[tt] * 8);
        float4 v0 = xr4[0], v1 = xr4[1];
        x[tt][0]=v0.x; x[tt][1]=v0.y; x[tt][2]=v0.z; x[tt][3]=v0.w;
        x[tt][4]=v1.x; x[tt][5]=v1.y; x[tt][6]=v1.z; x[tt][7]=v1.w;
        float sx = 0.f;
        unsigned m0 = 0, m1 = 0;
        #pragma unroll
        for (int j = 0; j < 8; j++) {
            sx += x[tt][j];
            if (x[tt][j] < 0.f)          m0 |= BITS[j];
            if (x[tt][j] + 0.25f < 0.f)  m1 |= BITS[j];
        }
        p1c[tt] = -0.5f * sx - 0.5f;
        maskx[tt][0] = m0;  px[tt][0] = (__popc(m0) & 1) << 31;
        maskx[tt][1] = m1;  px[tt][1] = (__popc(m1) & 1) << 31;
    }

    float best[2] = {-1e30f, -1e30f};
    int   bA[2]   = {0, 0};

    #pragma unroll
    for (int k = 0; k < 8; k++) {
        const int A = lane + (k << 5);
        float a[8];
        {
            const float4* p4 = reinterpret_cast<const float4*>(s_a[A]);
            float4 a0 = p4[0], a1 = p4[1];
            a[0]=a0.x; a[1]=a0.y; a[2]=a0.z; a[3]=a0.w;
            a[4]=a1.x; a[5]=a1.y; a[6]=a1.z; a[7]=a1.w;
        }
        const float nas  = s_a[A][8];
        const int   ns   = __float_as_int(nas);    // sign bit = sign(a7)
        const float nabs = fabsf(nas);

        #pragma unroll
        for (int tt = 0; tt < 2; tt++) {
            float t0[8], t1[8];
            #pragma unroll
            for (int j = 0; j < 8; j++) {
                t0[j] = x[tt][j] * a[j];                   // sign == sign(x_j)
                t1[j] = fmaf(0.25f, a[j], t0[j]);          // == (x+0.25)*|a| (1 rnd)
            }
            // p = 0
            float S0 = ((fabsf(t0[0]) + fabsf(t0[1])) + (fabsf(t0[2]) + fabsf(t0[3])))
                     + ((fabsf(t0[4]) + fabsf(t0[5])) + (fabsf(t0[6]) + fabsf(t0[7])));
            float mn0 = fminf(fminf(fminf(fabsf(t0[0]), fabsf(t0[1])),
                                    fminf(fabsf(t0[2]), fabsf(t0[3]))),
                              fminf(fminf(fabsf(t0[4]), fabsf(t0[5])),
                                    fminf(fabsf(t0[6]), fabsf(t0[7]))));
            float Sp0 = ((ns ^ px[tt][0]) < 0) ? fmaf(-2.f, mn0, S0) : S0;
            float sc0 = fmaf(2.f, Sp0, -nabs);
            // p = 1
            float S1 = ((fabsf(t1[0]) + fabsf(t1[1])) + (fabsf(t1[2]) + fabsf(t1[3])))
                     + ((fabsf(t1[4]) + fabsf(t1[5])) + (fabsf(t1[6]) + fabsf(t1[7])));
            float mn1 = fminf(fminf(fminf(fabsf(t1[0]), fabsf(t1[1])),
                                    fminf(fabsf(t1[2]), fabsf(t1[3]))),
                              fminf(fminf(fabsf(t1[4]), fabsf(t1[5])),
                                    fminf(fabsf(t1[6]), fabsf(t1[7]))));
            float Sp1 = ((ns ^ px[tt][1]) < 0) ? fmaf(-2.f, mn1, S1) : S1;
            float sc1 = fmaf(2.f, Sp1, -nabs) + p1c[tt];

            float scm = fmaxf(sc0, sc1);                   // parity re-decided at winner
            if (scm > best[tt]) { best[tt] = scm; bA[tt] = A; }   // first-wins: lowest A
        }
    }

    #pragma unroll
    for (int tt = 0; tt < 2; tt++) {
        // Warp argmax (butterfly; tie -> lowest A, matching argmax first-max).
        float b = best[tt]; int cA = bA[tt];
        #pragma unroll
        for (int off = 16; off; off >>= 1) {
            float ob = __shfl_xor_sync(0xffffffffu, b,  off);
            int   oc = __shfl_xor_sync(0xffffffffu, cA, off);
            if (ob > b || (ob == b && oc < cA)) { b = ob; cA = oc; }
        }

        // Winner recompute (all lanes, broadcast LDS): decide parity, sign mask,
        // argmin flip — identical formulas to the scan.
        const float* av = s_a[cA];
        const float nas  = av[8];
        const int   ns   = __float_as_int(nas);
        const float nabs = fabsf(nas);
        float t0[8], t1[8];
        #pragma unroll
        for (int j = 0; j < 8; j++) {
            t0[j] = x[tt][j] * av[j];
            t1[j] = fmaf(0.25f, av[j], t0[j]);
        }
        float S0 = ((fabsf(t0[0]) + fabsf(t0[1])) + (fabsf(t0[2]) + fabsf(t0[3])))
                 + ((fabsf(t0[4]) + fabsf(t0[5])) + (fabsf(t0[6]) + fabsf(t0[7])));
        float mn0 = fminf(fminf(fminf(fabsf(t0[0]), fabsf(t0[1])),
                                fminf(fabsf(t0[2]), fabsf(t0[3]))),
                          fminf(fminf(fabsf(t0[4]), fabsf(t0[5])),
                                fminf(fabsf(t0[6]), fabsf(t0[7]))));
        float Sp0 = ((ns ^ px[tt][0]) < 0) ? fmaf(-2.f, mn0, S0) : S0;
        float sc0 = fmaf(2.f, Sp0, -nabs);
        float S1 = ((fabsf(t1[0]) + fabsf(t1[1])) + (fabsf(t1[2]) + fabsf(t1[3])))
                 + ((fabsf(t1[4]) + fabsf(t1[5])) + (fabsf(t1[6]) + fabsf(t1[7])));
        float mn1 = fminf(fminf(fminf(fabsf(t1[0]), fabsf(t1[1])),
                                fminf(fabsf(t1[2]), fabsf(t1[3]))),
                          fminf(fminf(fabsf(t1[4]), fabsf(t1[5])),
                                fminf(fabsf(t1[6]), fabsf(t1[7]))));
        float Sp1 = ((ns ^ px[tt][1]) < 0) ? fmaf(-2.f, mn1, S1) : S1;
        float sc1 = fmaf(2.f, Sp1, -nabs) + p1c[tt];

        const int pw = (sc1 > sc0) ? 1 : 0;               // p0 wins exact ties
        unsigned m = maskx[tt][pw] ^ ((ns < 0) ? 0x80u : 0u);
        float mnv = 1e30f; unsigned mnbit = 0;
        #pragma unroll
        for (int j = 0; j < 8; j++) {
            float at = fabsf(pw ? t1[j] : t0[j]);
            if (at < mnv) { mnv = at; mnbit = BITS[j]; }  // strict: first min
        }
        if (__popc(m) & 1) m ^= mnbit;
        const int bestc = (cA << 8) | ((int)m ^ pw);      // p=1 flips sign-field bit 0

        if (lane < 8) {
            out[(size_t)row[tt] * 8 + lane] = grid[(size_t)bestc * 8 + lane];  // vals
        }
        if (lane == 0) {
            out[65536 + row[tt]] = (float)bestc;          // idxs
            s_bestc[tt * 8 + warp] = bestc;               // slot = tt*8 + (dm*4+dn)
        }
    }
    __syncthreads();

    // ---- Block-local _pack_idxs (int32 / x64-disabled semantics: the reference's
    //      sign32 << 32 saturates to 0 in XLA; packed = int32 wrap of abs32).
    if (tid < 4) {
        const int ttp = tid >> 1, jj = tid & 1;
        const int base = ttp * 8;
        const int j = 2 * jg0 + tid;                      // column-pair index 0..15
        int q00 = s_bestc[base +     2 * jj    ];         // (dm=0, dn=2jj)   -> (2i,   2j)
        int q10 = s_bestc[base + 4 + 2 * jj    ];         // (dm=1, dn=2jj)   -> (2i+1, 2j)
        int q01 = s_bestc[base +     2 * jj + 1];         // (dm=0, dn=2jj+1) -> (2i,   2j+1)
        int q11 = s_bestc[base + 4 + 2 * jj + 1];         // (dm=1, dn=2jj+1) -> (2i+1, 2j+1)

        unsigned abs32 = (unsigned)(q00 >> 8)
                       | ((unsigned)(q10 >> 8) << 8)
                       | ((unsigned)(q01 >> 8) << 16)
                       | ((unsigned)(q11 >> 8) << 24);

        // L from (i, j): L = (i>>3)<<7 | (j>>2)<<5 | (i&7)<<2 | (j&3)
        const int i = ipair;
        const int L = ((i >> 3) << 7) | ((j >> 2) << 5) | ((i & 7) << 2) | (j & 3);
        out[73728 + L] = (float)(int)abs32;               // int32 wrap, then f32 cast
    }
}

extern "C" void kernel_launch(void* const* d_in, const int* in_sizes, int n_in,
                              void* d_out, int out_size)
{
    const float* X         = (const float*)d_in[0];   // 256*32*8 = 65536
    const float* grid      = (const float*)d_in[1];   // 65536*8
    const float* grid_norm = (const float*)d_in[2];   // 65536
    float* out = (float*)d_out;                       // [vals | idxs | packed] fp32

    e8p_fused_kernel<<<512, 256>>>(X, grid, grid_norm, out);
}